// round 6
// baseline (speedup 1.0000x reference)
#include <cuda_runtime.h>
#include <math.h>

// Problem constants
#define BATCH     16384
#define NUM_F     32
#define EMBED     64
#define NPAIRS    496          // 32*31/2
#define THREADS   256

// x: [BATCH, 32, 64] f32  -> viewed as [BATCH, 512] float4
// out: [BATCH, 496] f32   -> row is 1984 bytes = 124 * float4 (16B aligned per row)
__global__ __launch_bounds__(THREADS, 8)
void opn_kernel(const float4* __restrict__ x, float4* __restrict__ out)
{
    const int b   = blockIdx.x;
    const int tid = threadIdx.x;

    __shared__ float s[NUM_F];

    // ---- load + reduce: field f = tid>>3, 8 threads per field, 8 floats each ----
    const float4* xb = x + (size_t)b * (NUM_F * EMBED / 4);   // 512 float4 per row
    const int f   = tid >> 3;
    const int sub = tid & 7;

    float4 a0 = xb[f * 16 + sub * 2 + 0];
    float4 a1 = xb[f * 16 + sub * 2 + 1];
    float v = (a0.x + a0.y) + (a0.z + a0.w) + (a1.x + a1.y) + (a1.z + a1.w);

    // reduce across the 8 lanes of this field (lane groups of 8 within a warp)
    v += __shfl_down_sync(0xffffffffu, v, 4);
    v += __shfl_down_sync(0xffffffffu, v, 2);
    v += __shfl_down_sync(0xffffffffu, v, 1);
    if (sub == 0) s[f] = v;
    __syncthreads();

    // ---- pairwise products: 124 float4 stores per row, threads 0..123 ----
    if (tid < NPAIRS / 4) {
        int p = tid * 4;

        // analytic p -> (i, j): start(i) = i*(63-i)/2, pairs ordered i asc, j asc
        float fi = (63.0f - sqrtf(3969.0f - 8.0f * (float)p)) * 0.5f;
        int i = (int)fi;
        // integer fix-up against float rounding
        int st = (i * (63 - i)) >> 1;
        while (st > p)                       { --i; st = (i * (63 - i)) >> 1; }
        while (((i + 1) * (62 - i)) >> 1 <= p) { ++i; st = (i * (63 - i)) >> 1; }
        int j = i + 1 + (p - st);

        float4 r;
        float* rp = &r.x;
        #pragma unroll
        for (int k = 0; k < 4; ++k) {
            rp[k] = s[i] * s[j];
            ++j;
            if (j == NUM_F) { ++i; j = i + 1; }
        }
        out[(size_t)b * (NPAIRS / 4) + tid] = r;
    }
}

extern "C" void kernel_launch(void* const* d_in, const int* in_sizes, int n_in,
                              void* d_out, int out_size)
{
    const float4* x   = (const float4*)d_in[0];
    float4*       out = (float4*)d_out;
    opn_kernel<<<BATCH, THREADS>>>(x, out);
}